// round 7
// baseline (speedup 1.0000x reference)
#include <cuda_runtime.h>
#include <cstdint>

// HolographicFMLayer: batched all-pairs circular convolution.
// inputs: float32 [B, 24, 64]  ->  out: float32 [B, 276, 64]
// out[b,p,n] = sum_k x[b,i,k] * x[b,j,(n-k) mod 64], pairs = triu_indices(24, k=1)
//
// CRT split: x^64-1 = (x^16-1)(x^16+1)(x^32+1)
//   per field: u = lo+hi, v = (lo-hi)/sqrt2; P=(u_lo+u_hi)/2, Q=(u_lo-u_hi)/2
//   per pair : d1 = cyclic16(P), d2 = negacyclic16(Q), c2 = negacyclic32(v)
//   recon    : c1[n<16]=d1+d2, c1[16..31]=d1-d2; out[n<32]=c1+c2, out[n+32]=c1-c2
//
// R6: flat pre-paired B operands in smem (Bp[t] = (B[t], B[t+8])), chunked
// read-only register files, FFMA2 with compile-time indices. No packed
// register is ever mutated -> no pair split/re-form MOV churn.

#define NF 24
#define NPAIR 276
#define LEN 64
#define THREADS 192
#define PAIRS_PER_BLOCK 92      // 3 blocks per batch
#define ACTIVE (PAIRS_PER_BLOCK * 2)
#define SV 65                   // V2 rows: 65 mod 32 == 1
#define SP 33                   // P2/Q2 rows: 33 mod 32 == 1

// float region (in floats)
#define OFF_V2 0
#define OFF_P2 (NF * SV)                  // 1560
#define OFF_Q2 (OFF_P2 + NF * SP + 24)    // +24 pad -> bank offset 16
#define FLOATS (OFF_Q2 + NF * SP)         // 3168 (even -> 8B aligned end)

// ULL region (in 8-byte units), strides mod 16 == 9 (odd -> conflict-free rows)
#define SPP 25
#define SVP 41
#define U_PP 0
#define U_QP (U_PP + NF * SPP + 1)        // +1 -> role bank-pair offset 9
#define U_VA (U_QP + NF * SPP + 1)
#define U_VB (U_VA + NF * SVP + 1)        // +985 mod 16 == 9
#define ULLS (U_VB + NF * SVP)

typedef unsigned long long ull;

// constexpr-built triu pair table in constant memory
struct PairTab { unsigned short ij[NPAIR]; };
static constexpr PairTab make_tab() {
    PairTab t{};
    int p = 0;
    for (int i = 0; i < NF; ++i)
        for (int j = i + 1; j < NF; ++j) { t.ij[p] = (unsigned short)(i * 32 + j); ++p; }
    return t;
}
__constant__ PairTab TAB = make_tab();

__device__ __forceinline__ ull packf2(float lo, float hi) {
    ull u;
    asm("mov.b64 %0, {%1, %2};" : "=l"(u)
        : "r"(__float_as_uint(lo)), "r"(__float_as_uint(hi)));
    return u;
}
__device__ __forceinline__ ull dupf2(float a) {
    ull u;
    asm("mov.b64 %0, {%1, %1};" : "=l"(u) : "r"(__float_as_uint(a)));
    return u;
}
__device__ __forceinline__ void fma2(ull& d, ull a, ull b) {
    asm("fma.rn.f32x2 %0, %1, %2, %0;" : "+l"(d) : "l"(a), "l"(b));
}
__device__ __forceinline__ ull mul2(ull a, ull b) {
    ull d; asm("mul.rn.f32x2 %0, %1, %2;" : "=l"(d) : "l"(a), "l"(b)); return d;
}
__device__ __forceinline__ ull add2(ull a, ull b) {
    ull d; asm("add.rn.f32x2 %0, %1, %2;" : "=l"(d) : "l"(a), "l"(b)); return d;
}
__device__ __forceinline__ ull sub2(ull a, ull b) {
    ull d; asm("sub.rn.f32x2 %0, %1, %2;" : "=l"(d) : "l"(a), "l"(b)); return d;
}
__device__ __forceinline__ float lo32(ull u) { return __uint_as_float((unsigned)u); }
__device__ __forceinline__ float hi32(ull u) { return __uint_as_float((unsigned)(u >> 32)); }

// acc[q] = sum_{k=0}^{N-1} A[N+k] (*2) Bp[q - k + N],  Bp read-only, chunked.
template <int N>
__device__ __forceinline__ void convflat(const ull* __restrict__ Bp,
                                         const float* __restrict__ A,
                                         ull* __restrict__ acc)
{
#pragma unroll
    for (int k0 = 0; k0 < N; k0 += 8) {
        ull bp[15];
#pragma unroll
        for (int s = 0; s < 15; ++s) bp[s] = Bp[N - k0 - 7 + s];
#pragma unroll
        for (int dk = 0; dk < 8; ++dk) {
            const ull aa = dupf2(A[N + k0 + dk]);
#pragma unroll
            for (int q = 0; q < 8; ++q) {
                if (k0 == 0 && dk == 0) acc[q] = mul2(aa, bp[q + 7]);
                else                    fma2(acc[q], aa, bp[q + 7 - dk]);
            }
        }
    }
}

__global__ __launch_bounds__(THREADS, 4)
void holo_flat_kernel(const float* __restrict__ in, float* __restrict__ out)
{
    __shared__ __align__(16) float smemf[FLOATS];
    __shared__ __align__(16) ull  smemu[ULLS];

    const int batch = blockIdx.x;
    const float* __restrict__ src = in + (size_t)batch * (NF * LEN);
    const int tid = threadIdx.x;

    // ---- fold phase 1: scalar extended arrays ----
    for (int idx = tid; idx < NF * 16; idx += THREADS) {
        const int f = idx >> 4, m = idx & 15;
        const float* x = src + f * LEN;
        const float x0 = x[m], x1 = x[m + 16], x2 = x[m + 32], x3 = x[m + 48];
        const float s = 0.70710678118654752f;
        const float vlo = (x0 - x2) * s, vhi = (x1 - x3) * s;
        const float ulo = x0 + x2,       uhi = x1 + x3;
        const float P = (ulo + uhi) * 0.5f, Q = (ulo - uhi) * 0.5f;
        float* V2 = smemf + OFF_V2 + f * SV;
        V2[m]      = -vlo;  V2[m + 16] = -vhi;
        V2[m + 32] =  vlo;  V2[m + 48] =  vhi;
        float* P2 = smemf + OFF_P2 + f * SP;
        P2[m] = P;  P2[m + 16] = P;
        float* Q2 = smemf + OFF_Q2 + f * SP;
        Q2[m] = -Q; Q2[m + 16] = Q;
    }
    __syncthreads();

    // ---- fold phase 2: pre-paired B operand arrays ----
    for (int e = tid; e < NF * 24; e += THREADS) {           // Ppair, Qpair
        const int f = e / 24, t = e - f * 24;
        const float* P2 = smemf + OFF_P2 + f * SP;
        const float* Q2 = smemf + OFF_Q2 + f * SP;
        smemu[U_PP + f * SPP + t] = packf2(P2[t], P2[t + 8]);
        smemu[U_QP + f * SPP + t] = packf2(Q2[t], Q2[t + 8]);
    }
    for (int e = tid; e < NF * 40; e += THREADS) {           // VpairA, VpairB
        const int f = e / 40, t = e - f * 40;
        const float* V2 = smemf + OFF_V2 + f * SV;
        smemu[U_VA + f * SVP + t] = packf2(V2[t],      V2[t + 8]);
        smemu[U_VB + f * SVP + t] = packf2(V2[t + 16], V2[t + 24]);
    }
    __syncthreads();

    const int role = tid & 1;
    int p = blockIdx.y * PAIRS_PER_BLOCK + (tid >> 1);
    const bool live = (tid < ACTIVE);
    if (p >= NPAIR) p = NPAIR - 1;        // tail threads duplicate work, no store
    const int ij = TAB.ij[p];
    const int i  = ij >> 5;
    const int j  = ij & 31;

    // ---- phase 1: one 16-conv each (role0: cyclic P, role1: negacyclic Q) ----
    const ull*   Bp16 = smemu + (role ? U_QP : U_PP) + j * SPP;
    const float* A16  = smemf + (role ? OFF_Q2 : OFF_P2) + i * SP;
    ull dmine[8];
    convflat<16>(Bp16, A16, dmine);        // dmine[q] = (d[q], d[q+8])

    // exchange between role threads (adjacent lanes), fold into c1
    ull c1[8];
#pragma unroll
    for (int q = 0; q < 8; ++q) {
        const ull dother = __shfl_xor_sync(0xFFFFFFFFu, dmine[q], 1);
        c1[q] = role ? sub2(dother, dmine[q]) : add2(dmine[q], dother);
    }

    // ---- phase 2: negacyclic-32, split by role ----
    const ull*   Bp32 = smemu + (role ? U_VB : U_VA) + j * SVP;
    const float* A32  = smemf + OFF_V2 + i * SV;
    ull av[8];
    convflat<32>(Bp32, A32, av);           // role0: (c2[q],c2[q+8]); role1: +16

    // ---- reconstruct & store ----
    if (live) {
        ull rp[8], rm[8];
#pragma unroll
        for (int q = 0; q < 8; ++q) {
            rp[q] = add2(c1[q], av[q]);    // out[base+q],  out[base+q+8]
            rm[q] = sub2(c1[q], av[q]);    // out[base+32+q], out[base+40+q]
        }
        const int base = role << 4;
        float4* __restrict__ dst =
            (float4*)(out + ((size_t)batch * NPAIR + p) * LEN + base);
        dst[0]  = make_float4(lo32(rp[0]), lo32(rp[1]), lo32(rp[2]), lo32(rp[3]));
        dst[1]  = make_float4(lo32(rp[4]), lo32(rp[5]), lo32(rp[6]), lo32(rp[7]));
        dst[2]  = make_float4(hi32(rp[0]), hi32(rp[1]), hi32(rp[2]), hi32(rp[3]));
        dst[3]  = make_float4(hi32(rp[4]), hi32(rp[5]), hi32(rp[6]), hi32(rp[7]));
        dst[8]  = make_float4(lo32(rm[0]), lo32(rm[1]), lo32(rm[2]), lo32(rm[3]));
        dst[9]  = make_float4(lo32(rm[4]), lo32(rm[5]), lo32(rm[6]), lo32(rm[7]));
        dst[10] = make_float4(hi32(rm[0]), hi32(rm[1]), hi32(rm[2]), hi32(rm[3]));
        dst[11] = make_float4(hi32(rm[4]), hi32(rm[5]), hi32(rm[6]), hi32(rm[7]));
    }
}

extern "C" void kernel_launch(void* const* d_in, const int* in_sizes, int n_in,
                              void* d_out, int out_size)
{
    const float* in  = (const float*)d_in[0];
    float*       out = (float*)d_out;
    const int batches = in_sizes[0] / (NF * LEN);   // 2048 for the bench shape
    dim3 grid(batches, 3);
    holo_flat_kernel<<<grid, THREADS>>>(in, out);
}

// round 10
// speedup vs baseline: 1.0715x; 1.0715x over previous
#include <cuda_runtime.h>
#include <cstdint>

// HolographicFMLayer: batched all-pairs circular convolution.
// inputs: float32 [B, 24, 64]  ->  out: float32 [B, 276, 64]
// out[b,p,n] = sum_k x[b,i,k] * x[b,j,(n-k) mod 64], pairs = triu_indices(24, k=1)
//
// CRT split: x^64-1 = (x^16-1)(x^16+1)(x^32+1)
//   per field: u = lo+hi, v = (lo-hi)/sqrt2; P=(u_lo+u_hi)/2, Q=(u_lo-u_hi)/2
//   per pair : d1 = cyclic16(P), d2 = negacyclic16(Q), c2 = negacyclic32(v)
//   recon    : c1[n<16]=d1+d2, c1[16..31]=d1-d2; out[n<32]=c1+c2, out[n+32]=c1-c2
// 1536 FMA/pair (vs 4096 direct).
//
// R7: ALL-SCALAR convolution engine (R1's proven sliding-window loop: ptxas
// renames scalar shifts to zero instructions; packed f32x2 variants R2-R6 all
// lost their pipe advantage to 64-bit pair-construction overhead).
// 2 threads per pair: role0 = cyclic16(P) + negacyclic32 outs[0:16],
//                     role1 = negacyclic16(Q) + negacyclic32 outs[16:32].

#define NF 24
#define NPAIR 276
#define LEN 64
#define THREADS 192
#define PAIRS_PER_BLOCK 92      // 3 blocks per batch
#define ACTIVE (PAIRS_PER_BLOCK * 2)
#define SV 65                   // 64-entry rows: 65 mod 32 == 1
#define SP 33                   // 32-entry rows: 33 mod 32 == 1
#define OFF_P (NF * SV)                 // 1560
#define OFF_Q (OFF_P + NF * SP + 24)    // +24 pad: (OFF_Q-OFF_P) mod 32 == 16
#define SMEM_FLOATS (OFF_Q + NF * SP)

// constexpr-built triu pair table in constant memory
struct PairTab { unsigned short ij[NPAIR]; };  // i*32 + j
static constexpr PairTab make_tab() {
    PairTab t{};
    int p = 0;
    for (int i = 0; i < NF; ++i)
        for (int j = i + 1; j < NF; ++j) { t.ij[p] = (unsigned short)(i * 32 + j); ++p; }
    return t;
}
__constant__ PairTab TAB = make_tab();

// Partial length-N convolution, 16 consecutive outputs starting at QOFF:
//   acc[q] = out[QOFF+q] = sum_{k=0}^{N-1} A[k+N] * B[QOFF+q-k+N]
// Scalar sliding window: at iter k, w[q] = B[QOFF+q+N-k]; shift renames free.
template <int N, int QOFF>
__device__ __forceinline__ void conv16s(const float* __restrict__ A,
                                        const float* __restrict__ B,
                                        float* __restrict__ acc)
{
    float w[16];
#pragma unroll
    for (int q = 0; q < 16; ++q) w[q] = B[QOFF + q + N];

    // k = 0 peeled as mul (no acc zero-init)
    {
        const float a = A[N];
#pragma unroll
        for (int q = 0; q < 16; ++q) acc[q] = a * w[q];
        const float nw = B[QOFF + N - 1];
#pragma unroll
        for (int q = 15; q > 0; --q) w[q] = w[q - 1];
        w[0] = nw;
    }
#pragma unroll
    for (int k = 1; k < N; ++k) {
        const float a = A[N + k];
#pragma unroll
        for (int q = 0; q < 16; ++q) acc[q] = fmaf(a, w[q], acc[q]);
        const float nw = B[QOFF + N - 1 - k];   // k==N-1 value unused; in-bounds
#pragma unroll
        for (int q = 15; q > 0; --q) w[q] = w[q - 1];
        w[0] = nw;
    }
}

__global__ __launch_bounds__(THREADS, 6)
void holo_crt_s_kernel(const float* __restrict__ in, float* __restrict__ out)
{
    __shared__ float smem[SMEM_FLOATS];
    float* __restrict__ bufV = smem;           // negacyclic-32 operand, scale 1/sqrt2
    float* __restrict__ bufP = smem + OFF_P;   // cyclic-16 operand (dup), scale 1/2
    float* __restrict__ bufQ = smem + OFF_Q;   // negacyclic-16 operand, scale 1/2

    const int batch = blockIdx.x;
    const float* __restrict__ src = in + (size_t)batch * (NF * LEN);
    const int tid = threadIdx.x;

    // ---- per-field folds ----
    for (int idx = tid; idx < NF * 16; idx += THREADS) {
        const int f = idx >> 4, m = idx & 15;
        const float* x = src + f * LEN;
        const float x0 = x[m], x1 = x[m + 16], x2 = x[m + 32], x3 = x[m + 48];
        const float s = 0.70710678118654752f;
        const float vlo = (x0 - x2) * s, vhi = (x1 - x3) * s;
        const float ulo = x0 + x2,       uhi = x1 + x3;
        const float P = (ulo + uhi) * 0.5f, Q = (ulo - uhi) * 0.5f;
        float* bV = bufV + f * SV;
        bV[m]      = -vlo;  bV[m + 16] = -vhi;
        bV[m + 32] =  vlo;  bV[m + 48] =  vhi;
        float* bP = bufP + f * SP;
        bP[m] = P;  bP[m + 16] = P;
        float* bQ = bufQ + f * SP;
        bQ[m] = -Q; bQ[m + 16] = Q;
    }
    __syncthreads();

    const int role = tid & 1;                          // lanes 2p, 2p+1 share a pair
    int p = blockIdx.y * PAIRS_PER_BLOCK + (tid >> 1);
    const bool live = (tid < ACTIVE);
    if (p >= NPAIR) p = NPAIR - 1;                     // tail threads duplicate, no store
    const int ij = TAB.ij[p];
    const int i  = ij >> 5;
    const int j  = ij & 31;

    // ---- phase 1: one 16-conv each (role0: cyclic P, role1: negacyclic Q) ----
    const float* A16 = (role ? bufQ : bufP) + i * SP;
    const float* B16 = (role ? bufQ : bufP) + j * SP;
    float d[16];
    conv16s<16, 0>(A16, B16, d);                       // d[q] = d_role[q]

    // exchange between role threads (adjacent lanes), fold into c1
    // role0: c1[n] = d1+d2 (n = q);  role1: c1[n] = d1-d2 (n = 16+q)
    float c1[16];
#pragma unroll
    for (int q = 0; q < 16; ++q) {
        const float other = __shfl_xor_sync(0xFFFFFFFFu, d[q], 1);
        c1[q] = role ? (other - d[q]) : (d[q] + other);
    }

    // ---- phase 2: negacyclic-32, 16 outputs per role ----
    const float* A32 = bufV + i * SV;
    const float* B32 = bufV + j * SV;
    float av[16];
    if (role == 0) conv16s<32, 0 >(A32, B32, av);      // av[q] = c2[q]
    else           conv16s<32, 16>(A32, B32, av);      // av[q] = c2[16+q]

    // ---- reconstruct & store ----
    if (live) {
        const int base = role << 4;  // 0 or 16
        float4* __restrict__ dst =
            (float4*)(out + ((size_t)batch * NPAIR + p) * LEN + base);
#pragma unroll
        for (int g = 0; g < 4; ++g) {
            dst[g] = make_float4(c1[4*g+0] + av[4*g+0], c1[4*g+1] + av[4*g+1],
                                 c1[4*g+2] + av[4*g+2], c1[4*g+3] + av[4*g+3]);
            dst[g + 8] = make_float4(c1[4*g+0] - av[4*g+0], c1[4*g+1] - av[4*g+1],
                                     c1[4*g+2] - av[4*g+2], c1[4*g+3] - av[4*g+3]);
        }
    }
}

extern "C" void kernel_launch(void* const* d_in, const int* in_sizes, int n_in,
                              void* d_out, int out_size)
{
    const float* in  = (const float*)d_in[0];
    float*       out = (float*)d_out;
    const int batches = in_sizes[0] / (NF * LEN);   // 2048 for the bench shape
    dim3 grid(batches, 3);
    holo_crt_s_kernel<<<grid, THREADS>>>(in, out);
}